// round 12
// baseline (speedup 1.0000x reference)
#include <cstdint>
#include <cuda_runtime.h>
#include <cuda_bf16.h>
#include <math_constants.h>

#define Bn 16
#define Sn 2048
#define Dn 768
#define D4 192                       // Dn/4
#define NORM_CONST 0.0360843918243516127f  // 1/sqrt(768)

#define NBLK 128                     // persistent grid (<= 148 SMs, all co-resident)
#define EPB 6                        // e-rows per block: 128*6 = 768
// attn geometry
#define CHUNK_ROWS 128
#define CHUNKS_PER_B 16
#define NCHUNK 256                   // 16 batches x 16 chunks
#define CPB 2                        // chunks per block: 128*2 = 256
#define ATT_STAGES 4
#define RPS 8
#define STAGE_F4 (RPS * D4)          // 1536 float4
#define STAGE_BYTES (STAGE_F4 * 16)  // 24576
#define NSTAGE_ITERS (CHUNK_ROWS / RPS)  // 16

// ---------------- scratch ----------------
__device__ float g_qk[Bn * Dn];
__device__ float g_pm[NCHUNK];
__device__ float g_pl[NCHUNK];
__device__ float g_pacc[(size_t)NCHUNK * Dn];
__device__ float g_c[Bn * Dn];
__device__ unsigned g_bar_count;     // zero-init; self-resetting
__device__ unsigned g_bar_gen;       // monotonically increasing across replays

// ---------------- helpers ----------------
__device__ __forceinline__ float warp_sum(float v) {
    #pragma unroll
    for (int off = 16; off > 0; off >>= 1)
        v += __shfl_xor_sync(0xffffffffu, v, off);
    return v;
}

__device__ __forceinline__ void cp_async16(unsigned int dst, const void* src) {
    asm volatile("cp.async.cg.shared.global [%0], [%1], 16;" :: "r"(dst), "l"(src));
}
__device__ __forceinline__ void cp_commit() {
    asm volatile("cp.async.commit_group;");
}
__device__ __forceinline__ void cp_wait_all() {
    asm volatile("cp.async.wait_group 0;");
}

// sense-reversal grid barrier; all NBLK blocks are co-resident (grid <= SM count).
// gen is read BEFORE arrival, so the releaser (which bumps gen only after all
// arrivals) can never race a waiter into a stale spin.
__device__ __forceinline__ void grid_barrier() {
    __syncthreads();
    if (threadIdx.x == 0) {
        __threadfence();
        unsigned gen = *(volatile unsigned*)&g_bar_gen;
        unsigned arrived = atomicAdd(&g_bar_count, 1u);
        if (arrived == NBLK - 1) {
            g_bar_count = 0;
            __threadfence();
            atomicAdd(&g_bar_gen, 1u);   // release
        } else {
            while (*(volatile unsigned*)&g_bar_gen == gen) __nanosleep(64);
        }
        __threadfence();
    }
    __syncthreads();
}

// ================= fused persistent kernel =================
__global__ void __launch_bounds__(256) fused_all(
    const float* __restrict__ b_in, const float* __restrict__ Wq,
    const float* __restrict__ Wk,  const float* __restrict__ Wv,
    float* __restrict__ out)
{
    extern __shared__ float smem[];           // 96 KB, reused across phases
    __shared__ float q0s[EPB * Bn];
    __shared__ float msm[8], lsm[8];
    int tid = threadIdx.x, warp = tid >> 5, lane = tid & 31;
    int blk = blockIdx.x;
    unsigned int sb = (unsigned int)__cvta_generic_to_shared(smem);

    // ---------- Phase 1: q0 = Wq x0 (6 e-rows), qk += Wk^T q0 (atomic) ----------
    {
        // preload all 16 x0 rows (48 KB) via cp.async
        const float4* src4 = (const float4*)b_in;
        #pragma unroll
        for (int i = 0; i < 12; i++) {
            int idx = i * 256 + tid;
            int b = idx / D4, d4 = idx - b * D4;
            cp_async16(sb + idx * 16, src4 + (size_t)b * Sn * D4 + d4);
        }
        cp_commit();

        // overlap: warps 0..5 load their Wq row
        int e = blk * EPB + warp;
        float4 wf[6];
        if (warp < EPB) {
            const float4* wr = (const float4*)(Wq + (size_t)e * Dn);
            #pragma unroll
            for (int i = 0; i < 6; i++) wf[i] = wr[i * 32 + lane];
        }
        cp_wait_all();
        __syncthreads();

        if (warp < EPB) {
            const float4* xs4 = (const float4*)smem;
            float acc[Bn];
            #pragma unroll
            for (int b = 0; b < Bn; b++) acc[b] = 0.f;
            #pragma unroll
            for (int i = 0; i < 6; i++) {
                float4 w = wf[i];
                #pragma unroll
                for (int b = 0; b < Bn; b++) {
                    float4 x = xs4[b * D4 + i * 32 + lane];
                    acc[b] = fmaf(w.x, x.x, fmaf(w.y, x.y, fmaf(w.z, x.z, fmaf(w.w, x.w, acc[b]))));
                }
            }
            #pragma unroll
            for (int b = 0; b < Bn; b++) {
                float v = warp_sum(acc[b]);
                if (lane == 0) q0s[warp * Bn + b] = v;
            }
        }
        __syncthreads();

        // qk partial: thread owns d = tid, tid+256, tid+512
        float a0[Bn], a1[Bn], a2[Bn];
        #pragma unroll
        for (int b = 0; b < Bn; b++) { a0[b] = a1[b] = a2[b] = 0.f; }
        #pragma unroll
        for (int ee = 0; ee < EPB; ee++) {
            const float* wkr = Wk + (size_t)(blk * EPB + ee) * Dn;
            float w0 = wkr[tid], w1 = wkr[tid + 256], w2 = wkr[tid + 512];
            #pragma unroll
            for (int b = 0; b < Bn; b++) {
                float q = q0s[ee * Bn + b];
                a0[b] = fmaf(q, w0, a0[b]);
                a1[b] = fmaf(q, w1, a1[b]);
                a2[b] = fmaf(q, w2, a2[b]);
            }
        }
        #pragma unroll
        for (int b = 0; b < Bn; b++) {
            atomicAdd(&g_qk[b * Dn + tid],       a0[b]);
            atomicAdd(&g_qk[b * Dn + tid + 256], a1[b]);
            atomicAdd(&g_qk[b * Dn + tid + 512], a2[b]);
        }
    }

    grid_barrier();   // qk complete

    // ---------- Phase 2: streaming online-softmax, 2 chunks per block ----------
    {
        float4* smem4 = (float4*)smem;
        for (int ci = 0; ci < CPB; ci++) {
            int id = blk * CPB + ci;             // 0..255
            int b = id >> 4, c = id & (CHUNKS_PER_B - 1);

            const float4* qkv = (const float4*)(g_qk + b * Dn);
            float4 qf[6];
            #pragma unroll
            for (int i = 0; i < 6; i++) qf[i] = qkv[i * 32 + lane];

            const float4* xb4 = (const float4*)b_in + ((size_t)b * Sn + (size_t)c * CHUNK_ROWS) * D4;

            #pragma unroll
            for (int s = 0; s < ATT_STAGES - 1; s++) {
                const float4* src = xb4 + (size_t)s * STAGE_F4;
                unsigned int dst = sb + s * STAGE_BYTES;
                #pragma unroll
                for (int i = 0; i < 6; i++) {
                    int idx = i * 256 + tid;
                    cp_async16(dst + idx * 16, src + idx);
                }
                cp_commit();
            }

            float m = -CUDART_INF_F, l = 0.f;
            float4 acc[6];
            #pragma unroll
            for (int i = 0; i < 6; i++) acc[i] = make_float4(0.f, 0.f, 0.f, 0.f);

            for (int t = 0; t < NSTAGE_ITERS; t++) {
                if (t + ATT_STAGES - 1 < NSTAGE_ITERS) {
                    int sn = t + ATT_STAGES - 1;
                    const float4* src = xb4 + (size_t)sn * STAGE_F4;
                    unsigned int dst = sb + (sn & (ATT_STAGES - 1)) * STAGE_BYTES;
                    #pragma unroll
                    for (int i = 0; i < 6; i++) {
                        int idx = i * 256 + tid;
                        cp_async16(dst + idx * 16, src + idx);
                    }
                }
                cp_commit();
                asm volatile("cp.async.wait_group 3;");
                __syncthreads();

                const float4* row = smem4 + (size_t)(t & (ATT_STAGES - 1)) * STAGE_F4 + warp * D4;
                float4 cur[6];
                #pragma unroll
                for (int i = 0; i < 6; i++) cur[i] = row[i * 32 + lane];

                float dot = 0.f;
                #pragma unroll
                for (int i = 0; i < 6; i++) {
                    dot = fmaf(qf[i].x, cur[i].x, dot);
                    dot = fmaf(qf[i].y, cur[i].y, dot);
                    dot = fmaf(qf[i].z, cur[i].z, dot);
                    dot = fmaf(qf[i].w, cur[i].w, dot);
                }
                float score = warp_sum(dot) * NORM_CONST;

                float mn = fmaxf(m, score);
                float corr = __expf(m - mn);
                float w = __expf(score - mn);
                l = l * corr + w;
                #pragma unroll
                for (int i = 0; i < 6; i++) {
                    acc[i].x = fmaf(w, cur[i].x, acc[i].x * corr);
                    acc[i].y = fmaf(w, cur[i].y, acc[i].y * corr);
                    acc[i].z = fmaf(w, cur[i].z, acc[i].z * corr);
                    acc[i].w = fmaf(w, cur[i].w, acc[i].w * corr);
                }
                m = mn;
                __syncthreads();
            }

            // merge 8 warp partials -> 1 chunk partial
            #pragma unroll
            for (int i = 0; i < 6; i++) smem4[warp * D4 + i * 32 + lane] = acc[i];
            if (lane == 0) { msm[warp] = m; lsm[warp] = l; }
            __syncthreads();

            if (tid < D4) {
                float M = -CUDART_INF_F;
                #pragma unroll
                for (int w = 0; w < 8; w++) M = fmaxf(M, msm[w]);
                float L = 0.f;
                float4 s = make_float4(0.f, 0.f, 0.f, 0.f);
                #pragma unroll
                for (int w = 0; w < 8; w++) {
                    float ef = __expf(msm[w] - M);
                    L = fmaf(ef, lsm[w], L);
                    float4 a = smem4[w * D4 + tid];
                    s.x = fmaf(ef, a.x, s.x);
                    s.y = fmaf(ef, a.y, s.y);
                    s.z = fmaf(ef, a.z, s.z);
                    s.w = fmaf(ef, a.w, s.w);
                }
                ((float4*)g_pacc)[(size_t)id * D4 + tid] = s;
                if (tid == 0) { g_pm[id] = M; g_pl[id] = L; }
            }
            __syncthreads();   // protect smem/msm before next chunk reuses them
        }
    }

    grid_barrier();   // all partials ready

    // ---------- Phase 3: split-softmax combine (blocks 0..15) ----------
    if (blk < Bn && tid < D4) {
        int b = blk, d4 = tid;
        const float* pm = g_pm + b * CHUNKS_PER_B;
        const float* pl = g_pl + b * CHUNKS_PER_B;
        float M = -CUDART_INF_F;
        #pragma unroll
        for (int j = 0; j < CHUNKS_PER_B; j++) M = fmaxf(M, pm[j]);
        float L = 0.f;
        float4 s = make_float4(0.f, 0.f, 0.f, 0.f);
        const float4* pacc4 = (const float4*)g_pacc;
        #pragma unroll
        for (int j = 0; j < CHUNKS_PER_B; j++) {
            float ef = __expf(pm[j] - M);
            L = fmaf(ef, pl[j], L);
            float4 a = pacc4[(size_t)(b * CHUNKS_PER_B + j) * D4 + d4];
            s.x = fmaf(ef, a.x, s.x);
            s.y = fmaf(ef, a.y, s.y);
            s.z = fmaf(ef, a.z, s.z);
            s.w = fmaf(ef, a.w, s.w);
        }
        float inv = 1.f / L;
        ((float4*)g_c)[b * D4 + d4] = make_float4(s.x * inv, s.y * inv, s.z * inv, s.w * inv);
    }

    grid_barrier();   // c ready

    // ---------- Phase 4: out[b][e] = Wv[e] . c[b]  (6 e-rows per block) ----------
    {
        // preload c (48 KB, L2-hot: just written)
        const float4* src4 = (const float4*)g_c;
        #pragma unroll
        for (int i = 0; i < 12; i++) {
            int idx = i * 256 + tid;
            cp_async16(sb + idx * 16, src4 + idx);
        }
        cp_commit();

        int e = blk * EPB + warp;
        float4 wf[6];
        if (warp < EPB) {
            const float4* wr = (const float4*)(Wv + (size_t)e * Dn);
            #pragma unroll
            for (int i = 0; i < 6; i++) wf[i] = wr[i * 32 + lane];
        }
        cp_wait_all();
        __syncthreads();

        if (warp < EPB) {
            const float4* xs4 = (const float4*)smem;
            float acc[Bn];
            #pragma unroll
            for (int b = 0; b < Bn; b++) acc[b] = 0.f;
            #pragma unroll
            for (int i = 0; i < 6; i++) {
                float4 w = wf[i];
                #pragma unroll
                for (int b = 0; b < Bn; b++) {
                    float4 x = xs4[b * D4 + i * 32 + lane];
                    acc[b] = fmaf(w.x, x.x, fmaf(w.y, x.y, fmaf(w.z, x.z, fmaf(w.w, x.w, acc[b]))));
                }
            }
            #pragma unroll
            for (int b = 0; b < Bn; b++) {
                float v = warp_sum(acc[b]);
                if (lane == 0) out[b * Dn + e] = v;
            }
        }
    }
}

// ---------------- launch ----------------
extern "C" void kernel_launch(void* const* d_in, const int* in_sizes, int n_in,
                              void* d_out, int out_size)
{
    const float* b_in = (const float*)d_in[0];
    // d_in[1] = mask (int64): masks whole QUERY rows only; query row 0 is always
    // unmasked and the output only uses query row 0 -> mask is irrelevant.
    const float* Wq = (const float*)d_in[2];
    const float* Wk = (const float*)d_in[3];
    const float* Wv = (const float*)d_in[4];
    float* out = (float*)d_out;

    float* qk; cudaGetSymbolAddress((void**)&qk, g_qk);

    cudaFuncSetAttribute(fused_all, cudaFuncAttributeMaxDynamicSharedMemorySize,
                         ATT_STAGES * STAGE_BYTES);

    cudaMemsetAsync(qk, 0, Bn * Dn * sizeof(float), 0);   // qk must be zero for atomics
    fused_all<<<NBLK, 256, ATT_STAGES * STAGE_BYTES>>>(b_in, Wq, Wk, Wv, out);
}

// round 14
// speedup vs baseline: 1.2440x; 1.2440x over previous
#include <cstdint>
#include <cuda_runtime.h>
#include <cuda_bf16.h>
#include <math_constants.h>

#define Bn 16
#define Sn 2048
#define Dn 768
#define D4 192                       // Dn/4
#define NORM_CONST 0.0360843918243516127f  // 1/sqrt(768)

// attn geometry
#define CHUNK_ROWS 128
#define CHUNKS_PER_B 16
#define NCHUNK 256                   // 16 batches x 16 chunks = persistent grid
#define ATT_STAGES 4
#define RPS 8
#define STAGE_F4 (RPS * D4)          // 1536 float4
#define STAGE_BYTES (STAGE_F4 * 16)  // 24576
#define NSTAGE_ITERS (CHUNK_ROWS / RPS)  // 16

#define NBLK 256                     // tail kernel grid; occ 2/SM -> all resident

// ---------------- scratch ----------------
__device__ float g_qk[Bn * Dn];
__device__ float g_pm[NCHUNK];
__device__ float g_pl[NCHUNK];
__device__ float g_pacc[(size_t)NCHUNK * Dn];
__device__ float g_c[Bn * Dn];
__device__ unsigned g_bar_count;     // zero-init; self-resetting
__device__ unsigned g_bar_gen;       // monotonic across replays

// ---------------- helpers ----------------
__device__ __forceinline__ float warp_sum(float v) {
    #pragma unroll
    for (int off = 16; off > 0; off >>= 1)
        v += __shfl_xor_sync(0xffffffffu, v, off);
    return v;
}

__device__ __forceinline__ void cp_async16(unsigned int dst, const void* src) {
    asm volatile("cp.async.cg.shared.global [%0], [%1], 16;" :: "r"(dst), "l"(src));
}
__device__ __forceinline__ void cp_commit() {
    asm volatile("cp.async.commit_group;");
}
__device__ __forceinline__ void cp_wait_all() {
    asm volatile("cp.async.wait_group 0;");
}

// sense-reversal grid barrier; requires all NBLK blocks co-resident
// (256 blocks, 2/SM at 96KB smem on 148 SMs). gen read BEFORE arrival.
__device__ __forceinline__ void grid_barrier() {
    __syncthreads();
    if (threadIdx.x == 0) {
        __threadfence();
        unsigned gen = *(volatile unsigned*)&g_bar_gen;
        unsigned arrived = atomicAdd(&g_bar_count, 1u);
        if (arrived == NBLK - 1) {
            g_bar_count = 0;
            __threadfence();
            atomicAdd(&g_bar_gen, 1u);
        } else {
            while (*(volatile unsigned*)&g_bar_gen == gen) __nanosleep(64);
        }
        __threadfence();
    }
    __syncthreads();
}

// ============ K1: fused q0 = Wq x0, qk += Wk^T q0 (per e-tile, atomic) ============
// grid 96 blocks; e-tile = 8 rows; Wq/Wk each streamed from DRAM exactly once.
__global__ void __launch_bounds__(256) fused_q0qk(
    float* __restrict__ qk, const float* __restrict__ Wq,
    const float* __restrict__ Wk, const float* __restrict__ b_in)
{
    extern __shared__ float xs[];             // 48 KB: x0 for all 16 batches
    __shared__ float q0s[8 * Bn];
    int tid = threadIdx.x, warp = tid >> 5, lane = tid & 31;
    int e0 = blockIdx.x * 8;

    {
        unsigned int sb = (unsigned int)__cvta_generic_to_shared(xs);
        const float4* src4 = (const float4*)b_in;
        #pragma unroll
        for (int i = 0; i < 12; i++) {
            int idx = i * 256 + tid;
            int b = idx / D4, d4 = idx - b * D4;
            cp_async16(sb + idx * 16, src4 + (size_t)b * Sn * D4 + d4);
        }
        cp_commit();
    }

    int e = e0 + warp;
    const float4* wr = (const float4*)(Wq + (size_t)e * Dn);
    float4 wf[6];
    #pragma unroll
    for (int i = 0; i < 6; i++) wf[i] = wr[i * 32 + lane];

    cp_wait_all();
    __syncthreads();

    {
        const float4* xs4 = (const float4*)xs;
        float acc[Bn];
        #pragma unroll
        for (int b = 0; b < Bn; b++) acc[b] = 0.f;
        #pragma unroll
        for (int i = 0; i < 6; i++) {
            float4 w = wf[i];
            #pragma unroll
            for (int b = 0; b < Bn; b++) {
                float4 x = xs4[b * D4 + i * 32 + lane];
                acc[b] = fmaf(w.x, x.x, fmaf(w.y, x.y, fmaf(w.z, x.z, fmaf(w.w, x.w, acc[b]))));
            }
        }
        #pragma unroll
        for (int b = 0; b < Bn; b++) {
            float v = warp_sum(acc[b]);
            if (lane == 0) q0s[warp * Bn + b] = v;
        }
    }
    __syncthreads();

    {
        float a0[Bn], a1[Bn], a2[Bn];
        #pragma unroll
        for (int b = 0; b < Bn; b++) { a0[b] = a1[b] = a2[b] = 0.f; }
        #pragma unroll
        for (int ee = 0; ee < 8; ee++) {
            const float* wkr = Wk + (size_t)(e0 + ee) * Dn;
            float w0 = wkr[tid], w1 = wkr[tid + 256], w2 = wkr[tid + 512];
            #pragma unroll
            for (int b = 0; b < Bn; b++) {
                float q = q0s[ee * Bn + b];
                a0[b] = fmaf(q, w0, a0[b]);
                a1[b] = fmaf(q, w1, a1[b]);
                a2[b] = fmaf(q, w2, a2[b]);
            }
        }
        #pragma unroll
        for (int b = 0; b < Bn; b++) {
            atomicAdd(&qk[b * Dn + tid],       a0[b]);
            atomicAdd(&qk[b * Dn + tid + 256], a1[b]);
            atomicAdd(&qk[b * Dn + tid + 512], a2[b]);
        }
    }
}

// ============ K2: persistent tail = attn streaming + combine + Wv matvec ============
// 256 blocks x 256 threads, 96 KB dyn smem, 2 blocks/SM co-resident.
__global__ void __launch_bounds__(256, 2) fused_tail(
    const float* __restrict__ b_in, const float* __restrict__ Wv,
    float* __restrict__ out)
{
    extern __shared__ float smem[];            // 96 KB, reused across phases
    __shared__ float msm[8], lsm[8];
    int tid = threadIdx.x, warp = tid >> 5, lane = tid & 31;
    int blk = blockIdx.x;
    unsigned int sb = (unsigned int)__cvta_generic_to_shared(smem);
    float4* smem4 = (float4*)smem;

    // ---------- Phase A: streaming online-softmax, 1 chunk per block ----------
    {
        int b = blk >> 4, c = blk & (CHUNKS_PER_B - 1);

        const float4* qkv = (const float4*)(g_qk + b * Dn);
        float4 qf[6];
        #pragma unroll
        for (int i = 0; i < 6; i++) qf[i] = qkv[i * 32 + lane];

        const float4* xb4 = (const float4*)b_in + ((size_t)b * Sn + (size_t)c * CHUNK_ROWS) * D4;

        #pragma unroll
        for (int s = 0; s < ATT_STAGES - 1; s++) {
            const float4* src = xb4 + (size_t)s * STAGE_F4;
            unsigned int dst = sb + s * STAGE_BYTES;
            #pragma unroll
            for (int i = 0; i < 6; i++) {
                int idx = i * 256 + tid;
                cp_async16(dst + idx * 16, src + idx);
            }
            cp_commit();
        }

        float m = -CUDART_INF_F, l = 0.f;
        float4 acc[6];
        #pragma unroll
        for (int i = 0; i < 6; i++) acc[i] = make_float4(0.f, 0.f, 0.f, 0.f);

        for (int t = 0; t < NSTAGE_ITERS; t++) {
            if (t + ATT_STAGES - 1 < NSTAGE_ITERS) {
                int sn = t + ATT_STAGES - 1;
                const float4* src = xb4 + (size_t)sn * STAGE_F4;
                unsigned int dst = sb + (sn & (ATT_STAGES - 1)) * STAGE_BYTES;
                #pragma unroll
                for (int i = 0; i < 6; i++) {
                    int idx = i * 256 + tid;
                    cp_async16(dst + idx * 16, src + idx);
                }
            }
            cp_commit();
            asm volatile("cp.async.wait_group 3;");
            __syncthreads();

            const float4* row = smem4 + (size_t)(t & (ATT_STAGES - 1)) * STAGE_F4 + warp * D4;
            float4 cur[6];
            #pragma unroll
            for (int i = 0; i < 6; i++) cur[i] = row[i * 32 + lane];

            float dot = 0.f;
            #pragma unroll
            for (int i = 0; i < 6; i++) {
                dot = fmaf(qf[i].x, cur[i].x, dot);
                dot = fmaf(qf[i].y, cur[i].y, dot);
                dot = fmaf(qf[i].z, cur[i].z, dot);
                dot = fmaf(qf[i].w, cur[i].w, dot);
            }
            float score = warp_sum(dot) * NORM_CONST;

            float mn = fmaxf(m, score);
            float corr = __expf(m - mn);
            float w = __expf(score - mn);
            l = l * corr + w;
            #pragma unroll
            for (int i = 0; i < 6; i++) {
                acc[i].x = fmaf(w, cur[i].x, acc[i].x * corr);
                acc[i].y = fmaf(w, cur[i].y, acc[i].y * corr);
                acc[i].z = fmaf(w, cur[i].z, acc[i].z * corr);
                acc[i].w = fmaf(w, cur[i].w, acc[i].w * corr);
            }
            m = mn;
            __syncthreads();
        }

        // merge 8 warp partials -> 1 chunk partial
        #pragma unroll
        for (int i = 0; i < 6; i++) smem4[warp * D4 + i * 32 + lane] = acc[i];
        if (lane == 0) { msm[warp] = m; lsm[warp] = l; }
        __syncthreads();

        if (tid < D4) {
            float M = -CUDART_INF_F;
            #pragma unroll
            for (int w = 0; w < 8; w++) M = fmaxf(M, msm[w]);
            float L = 0.f;
            float4 s = make_float4(0.f, 0.f, 0.f, 0.f);
            #pragma unroll
            for (int w = 0; w < 8; w++) {
                float ef = __expf(msm[w] - M);
                L = fmaf(ef, lsm[w], L);
                float4 a = smem4[w * D4 + tid];
                s.x = fmaf(ef, a.x, s.x);
                s.y = fmaf(ef, a.y, s.y);
                s.z = fmaf(ef, a.z, s.z);
                s.w = fmaf(ef, a.w, s.w);
            }
            ((float4*)g_pacc)[(size_t)blk * D4 + tid] = s;
            if (tid == 0) { g_pm[blk] = M; g_pl[blk] = L; }
        }
    }

    grid_barrier();   // all partials visible

    // ---------- Phase B: split-softmax combine (blocks 0..15) ----------
    if (blk < Bn && tid < D4) {
        int b = blk, d4 = tid;
        const float* pm = g_pm + b * CHUNKS_PER_B;
        const float* pl = g_pl + b * CHUNKS_PER_B;
        float M = -CUDART_INF_F;
        #pragma unroll
        for (int j = 0; j < CHUNKS_PER_B; j++) M = fmaxf(M, pm[j]);
        float L = 0.f;
        float4 s = make_float4(0.f, 0.f, 0.f, 0.f);
        const float4* pacc4 = (const float4*)g_pacc;
        #pragma unroll
        for (int j = 0; j < CHUNKS_PER_B; j++) {
            float ef = __expf(pm[j] - M);
            L = fmaf(ef, pl[j], L);
            float4 a = pacc4[(size_t)(b * CHUNKS_PER_B + j) * D4 + d4];
            s.x = fmaf(ef, a.x, s.x);
            s.y = fmaf(ef, a.y, s.y);
            s.z = fmaf(ef, a.z, s.z);
            s.w = fmaf(ef, a.w, s.w);
        }
        float inv = 1.f / L;
        ((float4*)g_c)[b * D4 + d4] = make_float4(s.x * inv, s.y * inv, s.z * inv, s.w * inv);
    }

    grid_barrier();   // c ready (L2-hot)

    // ---------- Phase C: out[b][e] = Wv[e] . c[b], 3 e-rows per block ----------
    {
        const float4* src4 = (const float4*)g_c;
        #pragma unroll
        for (int i = 0; i < 12; i++) {
            int idx = i * 256 + tid;
            cp_async16(sb + idx * 16, src4 + idx);
        }
        cp_commit();

        int e = blk * 3 + warp;                 // warps 0..2 active
        float4 wf[6];
        if (warp < 3) {
            const float4* wr = (const float4*)(Wv + (size_t)e * Dn);
            #pragma unroll
            for (int i = 0; i < 6; i++) wf[i] = wr[i * 32 + lane];
        }
        cp_wait_all();
        __syncthreads();

        if (warp < 3) {
            const float4* xs4 = (const float4*)smem;
            float acc[Bn];
            #pragma unroll
            for (int b = 0; b < Bn; b++) acc[b] = 0.f;
            #pragma unroll
            for (int i = 0; i < 6; i++) {
                float4 w = wf[i];
                #pragma unroll
                for (int b = 0; b < Bn; b++) {
                    float4 x = xs4[b * D4 + i * 32 + lane];
                    acc[b] = fmaf(w.x, x.x, fmaf(w.y, x.y, fmaf(w.z, x.z, fmaf(w.w, x.w, acc[b]))));
                }
            }
            #pragma unroll
            for (int b = 0; b < Bn; b++) {
                float v = warp_sum(acc[b]);
                if (lane == 0) out[b * Dn + e] = v;
            }
        }
    }
}

// ---------------- launch ----------------
extern "C" void kernel_launch(void* const* d_in, const int* in_sizes, int n_in,
                              void* d_out, int out_size)
{
    const float* b_in = (const float*)d_in[0];
    // d_in[1] = mask (int64): masks whole QUERY rows only; query row 0 is always
    // unmasked and the output only uses query row 0 -> mask is irrelevant.
    const float* Wq = (const float*)d_in[2];
    const float* Wk = (const float*)d_in[3];
    const float* Wv = (const float*)d_in[4];
    float* out = (float*)d_out;

    float* qk; cudaGetSymbolAddress((void**)&qk, g_qk);

    cudaFuncSetAttribute(fused_q0qk, cudaFuncAttributeMaxDynamicSharedMemorySize, 49152);
    cudaFuncSetAttribute(fused_tail, cudaFuncAttributeMaxDynamicSharedMemorySize,
                         ATT_STAGES * STAGE_BYTES);

    cudaMemsetAsync(qk, 0, Bn * Dn * sizeof(float), 0);
    fused_q0qk<<<96, 256, 49152>>>(qk, Wq, Wk, b_in);
    fused_tail<<<NBLK, 256, ATT_STAGES * STAGE_BYTES>>>(b_in, Wv, out);
}